// round 12
// baseline (speedup 1.0000x reference)
#include <cuda_runtime.h>
#include <cuda_fp16.h>

// Scratch (__device__ globals; zero-initialized at load). N = 100000 <= MAXN.
// All accumulators are read-then-zeroed inside the fused kernel, so every
// call starts from zeroed state (first call: static zero-init).
#define MAXN (1 << 17)
__device__ __align__(16) float  g_deg[MAXN];
__device__ __align__(16) float  g_dinv[MAXN];
__device__ __align__(16) __half g_a[MAXN];    // dinv[i]*x[i] (fp16)
__device__ __align__(16) float  g_S[MAXN];    // layer-1 aggregate (fp32 REDs)
__device__ __align__(16) __half g_u[MAXN];    // dinv[i]*t[i] (fp16)
__device__ __align__(16) float  g_acc[MAXN];  // layer-2 aggregate

// software grid-barrier counters (slots 0..4 = phase barriers, 5 = exit/reset)
__device__ unsigned g_cnt[8];

#define NT   256
#define OCC  8            // blocks per SM (32 regs x 256 thr x 8 = full RF)
#define NSM  148
#define NB   (NSM * OCC)  // 1184 = exactly one perfect-balance wave -> co-resident

// Software grid barrier. Safe: grid == 148*occ -> all blocks co-resident.
__device__ __forceinline__ void gridbar(int slot, unsigned nb) {
    __syncthreads();
    if (threadIdx.x == 0) {
        __threadfence();                       // release prior global writes
        atomicAdd(&g_cnt[slot], 1u);
        while (atomicAdd(&g_cnt[slot], 0u) < nb) __nanosleep(64);
        __threadfence();                       // acquire
    }
    __syncthreads();
}

__global__ void __launch_bounds__(NT, OCC)
gcn_fused(const float* __restrict__ x,
          const int* __restrict__ row, const int* __restrict__ col,
          const float* __restrict__ W1, const float* __restrict__ b1,
          const float* __restrict__ W2, const float* __restrict__ b2,
          float* __restrict__ out, int N, int E, int H, unsigned nb) {
    const int tid = blockIdx.x * NT + threadIdx.x;
    const int T   = gridDim.x * NT;
    const int E4  = E & ~3;

    // ---- P1: deg[col] += 1 (edge REDs) ----
    for (int e = tid * 4; e < E4; e += T * 4) {
        int4 c = __ldg(reinterpret_cast<const int4*>(col + e));
        atomicAdd(&g_deg[c.x], 1.0f);
        atomicAdd(&g_deg[c.y], 1.0f);
        atomicAdd(&g_deg[c.z], 1.0f);
        atomicAdd(&g_deg[c.w], 1.0f);
    }
    if (tid == 0)
        for (int e = E4; e < E; e++) atomicAdd(&g_deg[col[e]], 1.0f);
    gridbar(0, nb);

    // ---- P2: dinv = 1/sqrt(deg+1); a = dinv*x (fp16); zero deg ----
    for (int i = tid; i < N; i += T) {
        float d = g_deg[i];
        g_deg[i] = 0.0f;
        float di = 1.0f / sqrtf(d + 1.0f);     // +1 = self loop
        g_dinv[i] = di;
        g_a[i] = __float2half_rn(di * __ldg(x + i));
    }
    gridbar(1, nb);

    // ---- P3: S[col] += a[row] (gather + RED) ----
    for (int e = tid * 4; e < E4; e += T * 4) {
        int4 r = __ldg(reinterpret_cast<const int4*>(row + e));
        int4 c = __ldg(reinterpret_cast<const int4*>(col + e));
        float v0 = __half2float(__ldg(g_a + r.x));
        float v1 = __half2float(__ldg(g_a + r.y));
        float v2 = __half2float(__ldg(g_a + r.z));
        float v3 = __half2float(__ldg(g_a + r.w));
        atomicAdd(&g_S[c.x], v0);
        atomicAdd(&g_S[c.y], v1);
        atomicAdd(&g_S[c.z], v2);
        atomicAdd(&g_S[c.w], v3);
    }
    if (tid == 0)
        for (int e = E4; e < E; e++)
            atomicAdd(&g_S[col[e]], __half2float(g_a[row[e]]));
    gridbar(2, nb);

    // ---- P4: s = dinv*(S + a); t = MLP(s); u = dinv*t; zero S ----
    for (int i = tid; i < N; i += T) {
        float di = g_dinv[i];
        float Sv = g_S[i];
        g_S[i] = 0.0f;
        float s = di * (Sv + __half2float(g_a[i]));
        float acc = 0.0f;
        #pragma unroll 16
        for (int k = 0; k < H; k++) {
            float h = fmaf(__ldg(&W1[k]), s, __ldg(&b1[k]));
            h = fmaxf(h, 0.0f);
            acc = fmaf(h, __ldg(&W2[k]), acc);
        }
        g_u[i] = __float2half_rn(di * acc);
    }
    gridbar(3, nb);

    // ---- P5: acc[col] += u[row] ----
    for (int e = tid * 4; e < E4; e += T * 4) {
        int4 r = __ldg(reinterpret_cast<const int4*>(row + e));
        int4 c = __ldg(reinterpret_cast<const int4*>(col + e));
        float v0 = __half2float(__ldg(g_u + r.x));
        float v1 = __half2float(__ldg(g_u + r.y));
        float v2 = __half2float(__ldg(g_u + r.z));
        float v3 = __half2float(__ldg(g_u + r.w));
        atomicAdd(&g_acc[c.x], v0);
        atomicAdd(&g_acc[c.y], v1);
        atomicAdd(&g_acc[c.z], v2);
        atomicAdd(&g_acc[c.w], v3);
    }
    if (tid == 0)
        for (int e = E4; e < E; e++)
            atomicAdd(&g_acc[col[e]], __half2float(g_u[row[e]]));
    gridbar(4, nb);

    // ---- P6: out = dinv*(acc + u) + b2; zero acc ----
    float bb = __ldg(b2);
    for (int i = tid; i < N; i += T) {
        float av = g_acc[i];
        g_acc[i] = 0.0f;
        out[i] = g_dinv[i] * (av + __half2float(g_u[i])) + bb;
    }

    // ---- exit: last block to arrive resets all barrier counters ----
    __syncthreads();
    if (threadIdx.x == 0) {
        __threadfence();
        unsigned prev = atomicAdd(&g_cnt[5], 1u);
        if (prev + 1 == nb) {
            #pragma unroll
            for (int s = 0; s < 6; s++) g_cnt[s] = 0;
            __threadfence();
        }
    }
}

// ---------------------------------------------------------------------------
// Launch
// ---------------------------------------------------------------------------

extern "C" void kernel_launch(void* const* d_in, const int* in_sizes, int n_in,
                              void* d_out, int out_size) {
    const float* x    = (const float*)d_in[0];
    const int*   eidx = (const int*)d_in[1];    // [2, E] int32
    const float* W1   = (const float*)d_in[2];
    const float* b1   = (const float*)d_in[3];
    const float* W2   = (const float*)d_in[4];
    const float* b2   = (const float*)d_in[5];
    float*       out  = (float*)d_out;

    int N = in_sizes[0];
    int E = in_sizes[1] / 2;
    int H = in_sizes[3];

    const int* row = eidx;
    const int* col = eidx + E;

    gcn_fused<<<NB, NT>>>(x, row, col, W1, b1, W2, b2, out, N, E, H, (unsigned)NB);
}

// round 13
// speedup vs baseline: 1.6950x; 1.6950x over previous
#include <cuda_runtime.h>
#include <cuda_fp16.h>

// Scratch (__device__ globals; zero-init at load). N = 100000 <= MAXN.
// Rotated zeroing (R8 scheme): each accumulator re-zeroed by a later kernel
// in the same call, after its consumer has read it:
//   g_deg : atomics in deg_kernel -> read by prep  -> zeroed in scatter<0>
//   g_S   : atomics in scatter<0> -> read by t     -> zeroed in scatter<1>
//   g_acc : atomics in scatter<1> -> read by final -> zeroed in deg_kernel
#define MAXN (1 << 17)
__device__ __align__(16) float  g_deg[MAXN];
__device__ __align__(16) float  g_dinv[MAXN];
__device__ __align__(16) __half g_a[MAXN];    // dinv[i]*x[i]  (fp16)
__device__ __align__(16) float  g_S[MAXN];    // layer-1 aggregate (fp32 REDs)
__device__ __align__(16) __half g_u[MAXN];    // dinv[i]*t[i]  (fp16)
__device__ __align__(16) float  g_acc[MAXN];  // layer-2 aggregate

#define EPT 8          // edges/thread for deg_kernel
#define SB  296        // scatter blocks: 2 per SM (even/odd table halves)
#define ST  1024       // scatter threads/block; 2x1024 = 2048/SM = full

// ---------------------------------------------------------------------------
// Node kernels (exact R8 versions)
// ---------------------------------------------------------------------------

__global__ void prep_kernel(const float* __restrict__ x, int n) {
    int i4 = (blockIdx.x * blockDim.x + threadIdx.x) * 4;
    if (i4 + 3 < n) {
        float4 xv = *reinterpret_cast<const float4*>(x + i4);
        float4 dv = *reinterpret_cast<const float4*>(g_deg + i4);
        float4 di;
        di.x = 1.0f / sqrtf(dv.x + 1.0f);
        di.y = 1.0f / sqrtf(dv.y + 1.0f);
        di.z = 1.0f / sqrtf(dv.z + 1.0f);
        di.w = 1.0f / sqrtf(dv.w + 1.0f);
        *reinterpret_cast<float4*>(g_dinv + i4) = di;
        *reinterpret_cast<__half2*>(g_a + i4)     = __floats2half2_rn(di.x * xv.x, di.y * xv.y);
        *reinterpret_cast<__half2*>(g_a + i4 + 2) = __floats2half2_rn(di.z * xv.z, di.w * xv.w);
    } else {
        for (int i = i4; i < n; i++) {
            float di = 1.0f / sqrtf(g_deg[i] + 1.0f);
            g_dinv[i] = di;
            g_a[i] = __float2half_rn(di * x[i]);
        }
    }
}

__global__ void t_kernel(const float* __restrict__ W1,
                         const float* __restrict__ b1,
                         const float* __restrict__ W2,
                         int n, int H) {
    int i = blockIdx.x * blockDim.x + threadIdx.x;
    if (i < n) {
        float di = g_dinv[i];
        float s  = di * (g_S[i] + __half2float(g_a[i]));
        float acc = 0.0f;
        #pragma unroll 16
        for (int k = 0; k < H; k++) {
            float h = fmaf(__ldg(&W1[k]), s, __ldg(&b1[k]));
            h = fmaxf(h, 0.0f);
            acc = fmaf(h, __ldg(&W2[k]), acc);
        }
        g_u[i] = __float2half_rn(di * acc);
    }
}

__global__ void final_kernel(const float* __restrict__ b2,
                             float* __restrict__ out, int n) {
    int i = blockIdx.x * blockDim.x + threadIdx.x;
    if (i < n) {
        out[i] = g_dinv[i] * (g_acc[i] + __half2float(g_u[i])) + __ldg(&b2[0]);
    }
}

// ---------------------------------------------------------------------------
// Edge kernels
// ---------------------------------------------------------------------------

// deg[col] += 1 (at the REDG floor). Also zeroes g_acc.
__global__ void __launch_bounds__(256, 8)
deg_kernel(const int* __restrict__ col, int E, int N) {
    int i = blockIdx.x * blockDim.x + threadIdx.x;
    if (i < N) g_acc[i] = 0.0f;

    int e = i * EPT;
    if (e + EPT - 1 < E) {
        int idx[EPT];
        #pragma unroll
        for (int v = 0; v < EPT / 4; v++) {
            int4 c = *reinterpret_cast<const int4*>(col + e + v * 4);
            idx[v * 4 + 0] = c.x; idx[v * 4 + 1] = c.y;
            idx[v * 4 + 2] = c.z; idx[v * 4 + 3] = c.w;
        }
        #pragma unroll
        for (int v = 0; v < EPT; v++) atomicAdd(&g_deg[idx[v]], 1.0f);
    } else {
        for (; e < E; e++) atomicAdd(&g_deg[col[e]], 1.0f);
    }
}

// Half-table scatter: dst[col] += table[row].
// Even blocks cache table[0, Nh) in 100KB smem, odd blocks table[Nh, N).
// Each parity family scans ALL edges, processing only rows in its half
// -> every edge RED'd exactly once; gathers are LDS; full occupancy (2 blk/SM).
// PASS=0: g_a -> g_S (zeroes g_deg).  PASS=1: g_u -> g_acc (zeroes g_S).
template <int PASS>
__global__ void __launch_bounds__(ST, 2)
scatter_kernel(const int* __restrict__ row, const int* __restrict__ col,
               int E, int N, int Nh) {
    extern __shared__ __half sh[];   // Nh halves (~100KB)

    float* dst = (PASS == 0) ? g_S : g_acc;
    const __half* table = (PASS == 0) ? g_a : g_u;

    const int p    = blockIdx.x & 1;        // table half parity
    const int base = p ? Nh : 0;
    const int size = p ? (N - Nh) : Nh;

    // fused zeroing of the already-consumed accumulator
    int gtid = blockIdx.x * ST + threadIdx.x;
    if (gtid < N) {
        if (PASS == 0) g_deg[gtid] = 0.0f;
        else           g_S[gtid]   = 0.0f;
    }

    // cooperative smem copy of this block's table half (int4-coalesced;
    // base*2 is 16B-aligned since Nh is a multiple of 8; over-read past N
    // stays within MAXN -> safe)
    {
        int nvec = (size * 2 + 15) / 16;
        const int4* src4 = reinterpret_cast<const int4*>(table + base);
        int4* sh4 = reinterpret_cast<int4*>(sh);
        for (int v = threadIdx.x; v < nvec; v += ST) sh4[v] = src4[v];
    }
    __syncthreads();

    // family-wide grid stride over edge quads; predicate on row half
    const int fr  = blockIdx.x >> 1;                 // rank within parity family
    const int ftid = fr * ST + threadIdx.x;
    const int FT  = (gridDim.x >> 1) * ST;
    const int E4  = E & ~3;
    for (int e = ftid * 4; e < E4; e += FT * 4) {
        int4 r = __ldg(reinterpret_cast<const int4*>(row + e));
        int4 c = __ldg(reinterpret_cast<const int4*>(col + e));
        int r0 = r.x - base, r1 = r.y - base, r2 = r.z - base, r3 = r.w - base;
        if ((unsigned)r0 < (unsigned)size) atomicAdd(&dst[c.x], __half2float(sh[r0]));
        if ((unsigned)r1 < (unsigned)size) atomicAdd(&dst[c.y], __half2float(sh[r1]));
        if ((unsigned)r2 < (unsigned)size) atomicAdd(&dst[c.z], __half2float(sh[r2]));
        if ((unsigned)r3 < (unsigned)size) atomicAdd(&dst[c.w], __half2float(sh[r3]));
    }
    // tail (<4 edges): one thread per parity
    if (blockIdx.x < 2 && threadIdx.x == 0) {
        for (int e = E4; e < E; e++) {
            int rr = row[e] - base;
            if ((unsigned)rr < (unsigned)size)
                atomicAdd(&dst[col[e]], __half2float(sh[rr]));
        }
    }
}

// ---------------------------------------------------------------------------
// Launch
// ---------------------------------------------------------------------------

extern "C" void kernel_launch(void* const* d_in, const int* in_sizes, int n_in,
                              void* d_out, int out_size) {
    const float* x    = (const float*)d_in[0];
    const int*   eidx = (const int*)d_in[1];    // [2, E] int32
    const float* W1   = (const float*)d_in[2];
    const float* b1   = (const float*)d_in[3];
    const float* W2   = (const float*)d_in[4];
    const float* b2   = (const float*)d_in[5];
    float*       out  = (float*)d_out;

    int N = in_sizes[0];
    int E = in_sizes[1] / 2;
    int H = in_sizes[3];

    const int* row = eidx;
    const int* col = eidx + E;

    // half-table split point: multiple of 8 elements (16B-aligned fp16 base)
    int Nh = (((N + 1) / 2) + 7) & ~7;          // 50000 for N=100000
    int shBytes = ((Nh * 2) + 15) & ~15;        // ~100KB (even half is the larger)

    // Opt in to >48KB dynamic smem; idempotent, capture-safe, no allocation.
    cudaFuncSetAttribute(scatter_kernel<0>,
                         cudaFuncAttributeMaxDynamicSharedMemorySize, 113 * 1024);
    cudaFuncSetAttribute(scatter_kernel<1>,
                         cudaFuncAttributeMaxDynamicSharedMemorySize, 113 * 1024);

    const int TB = 256;
    int nodeBlocks  = (N + TB - 1) / TB;
    int node4Blocks = ((N + 3) / 4 + TB - 1) / TB;
    int edgeThreads = (E + EPT - 1) / EPT;
    int degBlocks   = (max(edgeThreads, N) + TB - 1) / TB;

    deg_kernel<<<degBlocks, TB>>>(col, E, N);
    prep_kernel<<<node4Blocks, TB>>>(x, N);
    scatter_kernel<0><<<SB, ST, shBytes>>>(row, col, E, N, Nh);
    t_kernel<<<nodeBlocks, TB>>>(W1, b1, W2, N, H);
    scatter_kernel<1><<<SB, ST, shBytes>>>(row, col, E, N, Nh);
    final_kernel<<<nodeBlocks, TB>>>(b2, out, N);
}

// round 14
// speedup vs baseline: 1.7974x; 1.0604x over previous
#include <cuda_runtime.h>
#include <cuda_fp16.h>

// Scratch (__device__ globals; zero-init at load). N = 100000 <= MAXN.
// Rotated zeroing (R8 scheme): each accumulator re-zeroed by a later kernel
// in the same call, after its consumer has read it:
//   g_deg : atomics in deg_kernel -> read by prep  -> zeroed in scatter<0>
//   g_S   : atomics in scatter<0> -> read by t     -> zeroed in scatter<1>
//   g_acc : atomics in scatter<1> -> read by final -> zeroed in deg_kernel
#define MAXN (1 << 17)
__device__ __align__(16) float  g_deg[MAXN];
__device__ __align__(16) float  g_dinv[MAXN];
__device__ __align__(16) __half g_a[MAXN];    // dinv[i]*x[i]  (fp16, 200KB: L1-resident)
__device__ __align__(16) float  g_S[MAXN];    // layer-1 aggregate (fp32 REDs)
__device__ __align__(16) __half g_u[MAXN];    // dinv[i]*t[i]  (fp16)
__device__ __align__(16) float  g_acc[MAXN];  // layer-2 aggregate

#define EPT  8   // edges/thread in deg_kernel
#define SEPT 4   // edges/thread in scatter kernels

// ---------------------------------------------------------------------------
// Node kernels (R8 versions)
// ---------------------------------------------------------------------------

__global__ void prep_kernel(const float* __restrict__ x, int n) {
    int i4 = (blockIdx.x * blockDim.x + threadIdx.x) * 4;
    if (i4 + 3 < n) {
        float4 xv = *reinterpret_cast<const float4*>(x + i4);
        float4 dv = *reinterpret_cast<const float4*>(g_deg + i4);
        float4 di;
        di.x = 1.0f / sqrtf(dv.x + 1.0f);
        di.y = 1.0f / sqrtf(dv.y + 1.0f);
        di.z = 1.0f / sqrtf(dv.z + 1.0f);
        di.w = 1.0f / sqrtf(dv.w + 1.0f);
        *reinterpret_cast<float4*>(g_dinv + i4) = di;
        *reinterpret_cast<__half2*>(g_a + i4)     = __floats2half2_rn(di.x * xv.x, di.y * xv.y);
        *reinterpret_cast<__half2*>(g_a + i4 + 2) = __floats2half2_rn(di.z * xv.z, di.w * xv.w);
    } else {
        for (int i = i4; i < n; i++) {
            float di = 1.0f / sqrtf(g_deg[i] + 1.0f);
            g_dinv[i] = di;
            g_a[i] = __float2half_rn(di * x[i]);
        }
    }
}

__global__ void t_kernel(const float* __restrict__ W1,
                         const float* __restrict__ b1,
                         const float* __restrict__ W2,
                         int n, int H) {
    int i = blockIdx.x * blockDim.x + threadIdx.x;
    if (i < n) {
        float di = g_dinv[i];
        float s  = di * (g_S[i] + __half2float(g_a[i]));
        float acc = 0.0f;
        #pragma unroll 16
        for (int k = 0; k < H; k++) {
            float h = fmaf(__ldg(&W1[k]), s, __ldg(&b1[k]));
            h = fmaxf(h, 0.0f);
            acc = fmaf(h, __ldg(&W2[k]), acc);
        }
        g_u[i] = __float2half_rn(di * acc);
    }
}

__global__ void final_kernel(const float* __restrict__ b2,
                             float* __restrict__ out, int n) {
    int i = blockIdx.x * blockDim.x + threadIdx.x;
    if (i < n) {
        out[i] = g_dinv[i] * (g_acc[i] + __half2float(g_u[i])) + __ldg(&b2[0]);
    }
}

// ---------------------------------------------------------------------------
// Edge kernels. Index streams use __ldcs (evict-first: keep them OUT of L1 so
// the 200KB fp16 gather table stays resident). Gathers use __ldg (allocate).
// ---------------------------------------------------------------------------

// deg[col] += 1 (REDG floor). Also zeroes g_acc.
__global__ void __launch_bounds__(256, 8)
deg_kernel(const int* __restrict__ col, int E, int N) {
    int i = blockIdx.x * blockDim.x + threadIdx.x;
    if (i < N) g_acc[i] = 0.0f;

    int e = i * EPT;
    if (e + EPT - 1 < E) {
        int idx[EPT];
        #pragma unroll
        for (int v = 0; v < EPT / 4; v++) {
            int4 c = __ldcs(reinterpret_cast<const int4*>(col + e + v * 4));
            idx[v * 4 + 0] = c.x; idx[v * 4 + 1] = c.y;
            idx[v * 4 + 2] = c.z; idx[v * 4 + 3] = c.w;
        }
        #pragma unroll
        for (int v = 0; v < EPT; v++) atomicAdd(&g_deg[idx[v]], 1.0f);
    } else {
        for (; e < E; e++) atomicAdd(&g_deg[col[e]], 1.0f);
    }
}

// Scatter pass: dst[col] += table[row].  Full occupancy (256thr x occ 8),
// LDG gathers against an L1-protected fp16 table, streaming index loads.
// PASS=0: g_a -> g_S (zeroes g_deg).  PASS=1: g_u -> g_acc (zeroes g_S).
template <int PASS>
__global__ void __launch_bounds__(256, 8)
scatter_kernel(const int* __restrict__ row, const int* __restrict__ col,
               int E, int N) {
    const __half* table = (PASS == 0) ? g_a : g_u;
    float* dst          = (PASS == 0) ? g_S : g_acc;

    int i = blockIdx.x * blockDim.x + threadIdx.x;

    // fused zeroing of the already-consumed accumulator
    if (i < N) {
        if (PASS == 0) g_deg[i] = 0.0f;
        else           g_S[i]   = 0.0f;
    }

    int e = i * SEPT;
    if (e + SEPT - 1 < E) {
        int4 r = __ldcs(reinterpret_cast<const int4*>(row + e));
        int4 c = __ldcs(reinterpret_cast<const int4*>(col + e));
        float v0 = __half2float(__ldg(table + r.x));
        float v1 = __half2float(__ldg(table + r.y));
        float v2 = __half2float(__ldg(table + r.z));
        float v3 = __half2float(__ldg(table + r.w));
        atomicAdd(&dst[c.x], v0);
        atomicAdd(&dst[c.y], v1);
        atomicAdd(&dst[c.z], v2);
        atomicAdd(&dst[c.w], v3);
    } else {
        for (; e < E; e++)
            atomicAdd(&dst[col[e]], __half2float(__ldg(table + row[e])));
    }
}

// ---------------------------------------------------------------------------
// Launch
// ---------------------------------------------------------------------------

extern "C" void kernel_launch(void* const* d_in, const int* in_sizes, int n_in,
                              void* d_out, int out_size) {
    const float* x    = (const float*)d_in[0];
    const int*   eidx = (const int*)d_in[1];    // [2, E] int32
    const float* W1   = (const float*)d_in[2];
    const float* b1   = (const float*)d_in[3];
    const float* W2   = (const float*)d_in[4];
    const float* b2   = (const float*)d_in[5];
    float*       out  = (float*)d_out;

    int N = in_sizes[0];
    int E = in_sizes[1] / 2;
    int H = in_sizes[3];

    const int* row = eidx;
    const int* col = eidx + E;

    const int TB = 256;
    int nodeBlocks  = (N + TB - 1) / TB;
    int node4Blocks = ((N + 3) / 4 + TB - 1) / TB;
    int degThreads  = (E + EPT - 1) / EPT;
    int degBlocks   = (max(degThreads, N) + TB - 1) / TB;
    int scatThreads = (E + SEPT - 1) / SEPT;
    int scatBlocks  = (max(scatThreads, N) + TB - 1) / TB;

    deg_kernel<<<degBlocks, TB>>>(col, E, N);
    prep_kernel<<<node4Blocks, TB>>>(x, N);
    scatter_kernel<0><<<scatBlocks, TB>>>(row, col, E, N);
    t_kernel<<<nodeBlocks, TB>>>(W1, b1, W2, N, H);
    scatter_kernel<1><<<scatBlocks, TB>>>(row, col, E, N);
    final_kernel<<<nodeBlocks, TB>>>(b2, out, N);
}